// round 11
// baseline (speedup 1.0000x reference)
#include <cuda_runtime.h>

// ShadingLayer: out[b,c,h,w] = sum_k L[b,c,k] * H_k(n[b,:,h,w])
// R10 = R2 champion exactly (8192 blocks x 256 thr, 2 float4-groups/thread,
//       6 front-batched LDG.128 streaming loads, reg-folded coefficients)
//       + st.global.wt write-through stores (output never re-read; keep L2
//       write-side pressure off the read stream).
//
// Converged series: DRAM ~6.05 TB/s (77% of 8TB/s) is the ceiling for this
// 1:1 R/W interleaved stream; R2's MLP=6 @ 40 regs / occ ~62% is optimal.
//
// d_in[0]: recnormalch fp32 (64,3,512,512)
// d_in[1]: fc_light    fp32 (64,27)
// d_out  : fp32 (64,3,512,512)

#define C1f 0.8862269254527580f
#define C2f 1.0233267079464885f
#define C3f 0.2477079561003757f
#define C4f 0.8580855308097834f
#define C5f 0.4290427654048917f

static __device__ __forceinline__ float4 ldcs4(const float* p) {
    return __ldcs(reinterpret_cast<const float4*>(p));
}
static __device__ __forceinline__ void stwt4(float* p, float4 v) {
    asm volatile("st.global.wt.v4.f32 [%0], {%1, %2, %3, %4};"
                 :: "l"(p), "f"(v.x), "f"(v.y), "f"(v.z), "f"(v.w)
                 : "memory");
}

__global__ __launch_bounds__(256)
void shading_kernel(const float* __restrict__ nrm,
                    const float* __restrict__ light,
                    float* __restrict__ out) {
    constexpr int HW = 512 * 512;          // pixels per plane
    // 65536 float4-groups/plane; 512 groups per block -> 128 blocks/batch
    const unsigned bid = blockIdx.x;
    const int b   = bid >> 7;              // batch
    const int blk = bid & 127;             // block within batch
    const int v0  = blk * 512 + threadIdx.x;

    // ---- front-batch all 6 data loads (MLP=6) ----
    const float* p0 = nrm + (size_t)b * 3 * HW + (size_t)v0 * 4;
    const float* p1 = p0 + 1024;           // +256 groups * 4 floats
    float4 X0 = ldcs4(p0);
    float4 Y0 = ldcs4(p0 + HW);
    float4 Z0 = ldcs4(p0 + 2 * HW);
    float4 X1 = ldcs4(p1);
    float4 Y1 = ldcs4(p1 + HW);
    float4 Z1 = ldcs4(p1 + 2 * HW);

    // ---- fold light coefficients (L2-broadcast, hidden under load latency) ----
    const float* Lb = light + b * 27;
    float a[3][9];
    #pragma unroll
    for (int c = 0; c < 3; c++) {
        a[c][0] = C1f * __ldg(Lb + 9 * c + 0);
        a[c][1] = C2f * __ldg(Lb + 9 * c + 1);
        a[c][2] = C2f * __ldg(Lb + 9 * c + 2);
        a[c][3] = C2f * __ldg(Lb + 9 * c + 3);
        a[c][4] = C3f * __ldg(Lb + 9 * c + 4);
        a[c][5] = C4f * __ldg(Lb + 9 * c + 5);
        a[c][6] = C4f * __ldg(Lb + 9 * c + 6);
        a[c][7] = C5f * __ldg(Lb + 9 * c + 7);
        a[c][8] = C4f * __ldg(Lb + 9 * c + 8);
    }

    float* q0 = out + (p0 - nrm);          // store base from load base

    #pragma unroll
    for (int g = 0; g < 2; g++) {
        const float4 X = g ? X1 : X0;
        const float4 Y = g ? Y1 : Y0;
        const float4 Z = g ? Z1 : Z0;
        const float xs[4] = {X.x, X.y, X.z, X.w};
        const float ys[4] = {Y.x, Y.y, Y.z, Y.w};
        const float zs[4] = {Z.x, Z.y, Z.z, Z.w};
        float o[3][4];

        #pragma unroll
        for (int j = 0; j < 4; j++) {
            const float x = xs[j], y = ys[j], z = zs[j];
            const float xx = x * x;
            const float yy = y * y;
            const float b5 = 2.0f * z * z - xx - yy;
            const float b6 = x * z;
            const float b7 = y * z;
            const float b8 = xx - yy;
            const float b9 = x * y;
            #pragma unroll
            for (int c = 0; c < 3; c++) {
                float r = a[c][0];
                r = fmaf(a[c][1], z,  r);
                r = fmaf(a[c][2], x,  r);
                r = fmaf(a[c][3], y,  r);
                r = fmaf(a[c][4], b5, r);
                r = fmaf(a[c][5], b6, r);
                r = fmaf(a[c][6], b7, r);
                r = fmaf(a[c][7], b8, r);
                r = fmaf(a[c][8], b9, r);
                o[c][j] = r;
            }
        }

        float* q = g ? (q0 + 1024) : q0;
        stwt4(q,          make_float4(o[0][0], o[0][1], o[0][2], o[0][3]));
        stwt4(q + HW,     make_float4(o[1][0], o[1][1], o[1][2], o[1][3]));
        stwt4(q + 2 * HW, make_float4(o[2][0], o[2][1], o[2][2], o[2][3]));
    }
}

extern "C" void kernel_launch(void* const* d_in, const int* in_sizes, int n_in,
                              void* d_out, int out_size) {
    const float* nrm   = (const float*)d_in[0];
    const float* light = (const float*)d_in[1];
    float* out = (float*)d_out;

    // 64 batches * 128 blocks = 8192 blocks, 256 threads, 2 groups/thread
    shading_kernel<<<8192, 256>>>(nrm, light, out);
}

// round 12
// speedup vs baseline: 1.0169x; 1.0169x over previous
#include <cuda_runtime.h>

// ShadingLayer: out[b,c,h,w] = sum_k L[b,c,k] * H_k(n[b,:,h,w])
// R11: R2's footprint via 256-bit memory ops (Blackwell LDG.256/STG.256).
//   - 8192 blocks x 256 thr; each thread: ONE float8 group per plane.
//   - 3x ld.global.cs.v8.f32 (96B read) + 3x st.global.cs.v8.f32 (96B write)
//     == R2's bytes/thread with HALF the LSU instructions; each warp op
//     covers 1024B = 8 full 128B lines.
//   - Tests whether the ~77% DRAM plateau has an issue-path component.
//
// d_in[0]: recnormalch fp32 (64,3,512,512)
// d_in[1]: fc_light    fp32 (64,27)
// d_out  : fp32 (64,3,512,512)

#define C1f 0.8862269254527580f
#define C2f 1.0233267079464885f
#define C3f 0.2477079561003757f
#define C4f 0.8580855308097834f
#define C5f 0.4290427654048917f

static __device__ __forceinline__ void ldcs8(const float* p, float4& lo, float4& hi) {
    asm("ld.global.cs.v8.f32 {%0,%1,%2,%3,%4,%5,%6,%7}, [%8];"
        : "=f"(lo.x), "=f"(lo.y), "=f"(lo.z), "=f"(lo.w),
          "=f"(hi.x), "=f"(hi.y), "=f"(hi.z), "=f"(hi.w)
        : "l"(p));
}
static __device__ __forceinline__ void stcs8(float* p, const float4 lo, const float4 hi) {
    asm volatile("st.global.cs.v8.f32 [%0], {%1,%2,%3,%4,%5,%6,%7,%8};"
                 :: "l"(p),
                    "f"(lo.x), "f"(lo.y), "f"(lo.z), "f"(lo.w),
                    "f"(hi.x), "f"(hi.y), "f"(hi.z), "f"(hi.w)
                 : "memory");
}

__global__ __launch_bounds__(256)
void shading_kernel(const float* __restrict__ nrm,
                    const float* __restrict__ light,
                    float* __restrict__ out) {
    constexpr int HW = 512 * 512;           // pixels per plane
    // 32768 float8-groups/plane; 256 per block -> 128 blocks/batch
    const unsigned bid = blockIdx.x;
    const int b   = bid >> 7;               // batch
    const int blk = bid & 127;              // block within batch
    const int v0  = blk * 256 + threadIdx.x;   // float8 group index

    // ---- front-batch all 3 x 32B loads (same bytes in flight as R2) ----
    const float* p0 = nrm + (size_t)b * 3 * HW + (size_t)v0 * 8;
    float4 Xl, Xh, Yl, Yh, Zl, Zh;
    ldcs8(p0,          Xl, Xh);
    ldcs8(p0 + HW,     Yl, Yh);
    ldcs8(p0 + 2 * HW, Zl, Zh);

    // ---- fold light coefficients (hidden under load latency) ----
    const float* Lb = light + b * 27;
    float a[3][9];
    #pragma unroll
    for (int c = 0; c < 3; c++) {
        a[c][0] = C1f * __ldg(Lb + 9 * c + 0);
        a[c][1] = C2f * __ldg(Lb + 9 * c + 1);
        a[c][2] = C2f * __ldg(Lb + 9 * c + 2);
        a[c][3] = C2f * __ldg(Lb + 9 * c + 3);
        a[c][4] = C3f * __ldg(Lb + 9 * c + 4);
        a[c][5] = C4f * __ldg(Lb + 9 * c + 5);
        a[c][6] = C4f * __ldg(Lb + 9 * c + 6);
        a[c][7] = C5f * __ldg(Lb + 9 * c + 7);
        a[c][8] = C4f * __ldg(Lb + 9 * c + 8);
    }

    const float xs[8] = {Xl.x, Xl.y, Xl.z, Xl.w, Xh.x, Xh.y, Xh.z, Xh.w};
    const float ys[8] = {Yl.x, Yl.y, Yl.z, Yl.w, Yh.x, Yh.y, Yh.z, Yh.w};
    const float zs[8] = {Zl.x, Zl.y, Zl.z, Zl.w, Zh.x, Zh.y, Zh.z, Zh.w};

    float o[3][8];
    #pragma unroll
    for (int j = 0; j < 8; j++) {
        const float x = xs[j], y = ys[j], z = zs[j];
        const float xx = x * x;
        const float yy = y * y;
        const float b5 = 2.0f * z * z - xx - yy;
        const float b6 = x * z;
        const float b7 = y * z;
        const float b8 = xx - yy;
        const float b9 = x * y;
        #pragma unroll
        for (int c = 0; c < 3; c++) {
            float r = a[c][0];
            r = fmaf(a[c][1], z,  r);
            r = fmaf(a[c][2], x,  r);
            r = fmaf(a[c][3], y,  r);
            r = fmaf(a[c][4], b5, r);
            r = fmaf(a[c][5], b6, r);
            r = fmaf(a[c][6], b7, r);
            r = fmaf(a[c][7], b8, r);
            r = fmaf(a[c][8], b9, r);
            o[c][j] = r;
        }
    }

    float* q0 = out + (p0 - nrm);           // store base from load base
    #pragma unroll
    for (int c = 0; c < 3; c++) {
        stcs8(q0 + (size_t)c * HW,
              make_float4(o[c][0], o[c][1], o[c][2], o[c][3]),
              make_float4(o[c][4], o[c][5], o[c][6], o[c][7]));
    }
}

extern "C" void kernel_launch(void* const* d_in, const int* in_sizes, int n_in,
                              void* d_out, int out_size) {
    const float* nrm   = (const float*)d_in[0];
    const float* light = (const float*)d_in[1];
    float* out = (float*)d_out;

    // 64 batches * 128 blocks = 8192 blocks, 256 threads, 8 pixels/thread
    shading_kernel<<<8192, 256>>>(nrm, light, out);
}

// round 13
// speedup vs baseline: 1.0225x; 1.0055x over previous
#include <cuda_runtime.h>

// ShadingLayer: out[b,c,h,w] = sum_k L[b,c,k] * H_k(n[b,:,h,w])
// R12 = R11 (256-bit LDG/STG, best ncu time of the series: 56.7us, DRAM 77.2%)
//       + 32-bit unsigned offset addressing (cut alu% from 64-bit pointer
//       chains), shared batch-base for loads and stores.
//
// Series: ~6.1 TB/s (77%) is this 1:1 R/W stream's DRAM ceiling; MLP=3x256bit
// @ 40 regs / occ 64% sits on it with minimal issue overhead.
//
// d_in[0]: recnormalch fp32 (64,3,512,512)
// d_in[1]: fc_light    fp32 (64,27)
// d_out  : fp32 (64,3,512,512)

#define C1f 0.8862269254527580f
#define C2f 1.0233267079464885f
#define C3f 0.2477079561003757f
#define C4f 0.8580855308097834f
#define C5f 0.4290427654048917f

static __device__ __forceinline__ void ldcs8(const float* p, float4& lo, float4& hi) {
    asm("ld.global.cs.v8.f32 {%0,%1,%2,%3,%4,%5,%6,%7}, [%8];"
        : "=f"(lo.x), "=f"(lo.y), "=f"(lo.z), "=f"(lo.w),
          "=f"(hi.x), "=f"(hi.y), "=f"(hi.z), "=f"(hi.w)
        : "l"(p));
}
static __device__ __forceinline__ void stcs8(float* p, const float4 lo, const float4 hi) {
    asm volatile("st.global.cs.v8.f32 [%0], {%1,%2,%3,%4,%5,%6,%7,%8};"
                 :: "l"(p),
                    "f"(lo.x), "f"(lo.y), "f"(lo.z), "f"(lo.w),
                    "f"(hi.x), "f"(hi.y), "f"(hi.z), "f"(hi.w)
                 : "memory");
}

__global__ __launch_bounds__(256)
void shading_kernel(const float* __restrict__ nrm,
                    const float* __restrict__ light,
                    float* __restrict__ out) {
    constexpr unsigned HW = 512u * 512u;     // pixels per plane
    // 32768 float8-groups/plane; 256 per block -> 128 blocks/batch
    const unsigned bid = blockIdx.x;
    const unsigned b   = bid >> 7;           // batch
    const unsigned blk = bid & 127u;         // block within batch

    // single 32-bit element offset shared by loads and stores
    const unsigned base = b * (3u * HW) + ((blk << 8) + threadIdx.x) * 8u;

    const float* pin  = nrm + base;
    float*       pout = out + base;

    // ---- front-batch all 3 x 32B loads ----
    float4 Xl, Xh, Yl, Yh, Zl, Zh;
    ldcs8(pin,           Xl, Xh);
    ldcs8(pin + HW,      Yl, Yh);
    ldcs8(pin + 2u * HW, Zl, Zh);

    // ---- fold light coefficients (one burst, hidden under load latency) ----
    const float* Lb = light + b * 27u;
    float L[27];
    #pragma unroll
    for (int i = 0; i < 27; i++) L[i] = __ldg(Lb + i);

    float a[3][9];
    #pragma unroll
    for (int c = 0; c < 3; c++) {
        a[c][0] = C1f * L[9 * c + 0];
        a[c][1] = C2f * L[9 * c + 1];
        a[c][2] = C2f * L[9 * c + 2];
        a[c][3] = C2f * L[9 * c + 3];
        a[c][4] = C3f * L[9 * c + 4];
        a[c][5] = C4f * L[9 * c + 5];
        a[c][6] = C4f * L[9 * c + 6];
        a[c][7] = C5f * L[9 * c + 7];
        a[c][8] = C4f * L[9 * c + 8];
    }

    const float xs[8] = {Xl.x, Xl.y, Xl.z, Xl.w, Xh.x, Xh.y, Xh.z, Xh.w};
    const float ys[8] = {Yl.x, Yl.y, Yl.z, Yl.w, Yh.x, Yh.y, Yh.z, Yh.w};
    const float zs[8] = {Zl.x, Zl.y, Zl.z, Zl.w, Zh.x, Zh.y, Zh.z, Zh.w};

    float o[3][8];
    #pragma unroll
    for (int j = 0; j < 8; j++) {
        const float x = xs[j], y = ys[j], z = zs[j];
        const float xx = x * x;
        const float yy = y * y;
        const float b5 = 2.0f * z * z - xx - yy;
        const float b6 = x * z;
        const float b7 = y * z;
        const float b8 = xx - yy;
        const float b9 = x * y;
        #pragma unroll
        for (int c = 0; c < 3; c++) {
            float r = a[c][0];
            r = fmaf(a[c][1], z,  r);
            r = fmaf(a[c][2], x,  r);
            r = fmaf(a[c][3], y,  r);
            r = fmaf(a[c][4], b5, r);
            r = fmaf(a[c][5], b6, r);
            r = fmaf(a[c][6], b7, r);
            r = fmaf(a[c][7], b8, r);
            r = fmaf(a[c][8], b9, r);
            o[c][j] = r;
        }
    }

    stcs8(pout,
          make_float4(o[0][0], o[0][1], o[0][2], o[0][3]),
          make_float4(o[0][4], o[0][5], o[0][6], o[0][7]));
    stcs8(pout + HW,
          make_float4(o[1][0], o[1][1], o[1][2], o[1][3]),
          make_float4(o[1][4], o[1][5], o[1][6], o[1][7]));
    stcs8(pout + 2u * HW,
          make_float4(o[2][0], o[2][1], o[2][2], o[2][3]),
          make_float4(o[2][4], o[2][5], o[2][6], o[2][7]));
}

extern "C" void kernel_launch(void* const* d_in, const int* in_sizes, int n_in,
                              void* d_out, int out_size) {
    const float* nrm   = (const float*)d_in[0];
    const float* light = (const float*)d_in[1];
    float* out = (float*)d_out;

    // 64 batches * 128 blocks = 8192 blocks, 256 threads, 8 pixels/thread
    shading_kernel<<<8192, 256>>>(nrm, light, out);
}